// round 3
// baseline (speedup 1.0000x reference)
#include <cuda_runtime.h>
#include <cuda_bf16.h>
#include <math.h>
#include <stdint.h>

#define NB 8
#define NT 8192
#define ND 128
#define NH 8
#define TILE 128

// ---------------- scratch (device globals; no allocs allowed) ---------------
static __device__ float g_ctx[NB * NH * 16 * 16];   // [b][h][d][e]
static __device__ float g_ksum[NB * 128];           // [b][h*16+d]

// ---------------------------------------------------------------------------
// mma.sync m16n8k16 bf16 (baseline PTX, works on plain sm_103 target)
// ---------------------------------------------------------------------------
__device__ __forceinline__ void mma16816(float c[4], const uint32_t a[4],
                                         uint32_t b0, uint32_t b1) {
    asm volatile(
        "mma.sync.aligned.m16n8k16.row.col.f32.bf16.bf16.f32 "
        "{%0,%1,%2,%3}, {%4,%5,%6,%7}, {%8,%9}, {%0,%1,%2,%3};"
        : "+f"(c[0]), "+f"(c[1]), "+f"(c[2]), "+f"(c[3])
        : "r"(a[0]), "r"(a[1]), "r"(a[2]), "r"(a[3]), "r"(b0), "r"(b1));
}

// Tile layout (A and W identical): [128 rows][128 bf16 = 256B], with 16B-granule
// XOR swizzle: phys = row*256 + (((k>>3) ^ (row&7))<<4) + (k&7)*2.
// Fragment loads are conflict-free: 8 rows x 4 lanes per 16B granule.

// bf16 hi/lo split store of 4 consecutive-k fp32 values into A tiles.
__device__ __forceinline__ void a_store4(char* hi, char* lo, int row, int k4, float4 v) {
    uint32_t off = (uint32_t)(row * 256 + ((((k4 >> 1) ^ (row & 7)) << 4) | ((k4 & 1) << 3)));
    __nv_bfloat16 h0 = __float2bfloat16(v.x), h1 = __float2bfloat16(v.y);
    __nv_bfloat16 h2 = __float2bfloat16(v.z), h3 = __float2bfloat16(v.w);
    *(__nv_bfloat162*)(hi + off)     = __halves2bfloat162(h0, h1);
    *(__nv_bfloat162*)(hi + off + 4) = __halves2bfloat162(h2, h3);
    __nv_bfloat16 l0 = __float2bfloat16(v.x - __bfloat162float(h0));
    __nv_bfloat16 l1 = __float2bfloat16(v.y - __bfloat162float(h1));
    __nv_bfloat16 l2 = __float2bfloat16(v.z - __bfloat162float(h2));
    __nv_bfloat16 l3 = __float2bfloat16(v.w - __bfloat162float(h3));
    *(__nv_bfloat162*)(lo + off)     = __halves2bfloat162(l0, l1);
    *(__nv_bfloat162*)(lo + off + 4) = __halves2bfloat162(l2, l3);
}

// Convert W fp32 [k][n] row-major -> Wt[n][k] bf16 swizzled (one polarity).
__device__ __forceinline__ void convert_w(const float* __restrict__ W, char* wt,
                                          bool lo, int tid) {
    const float4* Wp = (const float4*)W;
    for (int i = tid; i < 4096; i += 256) {
        int k = i >> 5, n4 = i & 31;
        float4 w = Wp[i];
        float vv[4] = {w.x, w.y, w.z, w.w};
        #pragma unroll
        for (int u = 0; u < 4; u++) {
            int n = n4 * 4 + u;
            float val = vv[u];
            __nv_bfloat16 bh = __float2bfloat16(val);
            if (lo) bh = __float2bfloat16(val - __bfloat162float(bh));
            *(__nv_bfloat16*)(wt + n * 256 +
                ((((k >> 3) ^ (n & 7)) << 4) | ((k & 7) * 2))) = bh;
        }
    }
}

// One product pass: acc += A(At) @ Wt^T-frag, K=128.
__device__ __forceinline__ void gemm_product(const char* __restrict__ At,
                                             const char* __restrict__ Wt,
                                             float acc[2][8][4],
                                             int r0, int c0, int qid, int tg) {
    #pragma unroll
    for (int ks = 0; ks < 8; ks++) {
        const uint32_t g0 = (uint32_t)((((2 * ks) ^ qid) << 4) + tg * 4);
        const uint32_t g1 = (uint32_t)((((2 * ks + 1) ^ qid) << 4) + tg * 4);
        uint32_t A[2][4];
        #pragma unroll
        for (int mt = 0; mt < 2; mt++) {
            const char* base = At + (r0 + mt * 16 + qid) * 256;
            A[mt][0] = *(const uint32_t*)(base + g0);
            A[mt][1] = *(const uint32_t*)(base + 8 * 256 + g0);
            A[mt][2] = *(const uint32_t*)(base + g1);
            A[mt][3] = *(const uint32_t*)(base + 8 * 256 + g1);
        }
        #pragma unroll
        for (int nt = 0; nt < 8; nt++) {
            const char* bb = Wt + (c0 + nt * 8 + qid) * 256;
            uint32_t b0 = *(const uint32_t*)(bb + g0);
            uint32_t b1 = *(const uint32_t*)(bb + g1);
            mma16816(acc[0][nt], A[0], b0, b1);
            mma16816(acc[1][nt], A[1], b0, b1);
        }
    }
}

// Full fp32-accurate GEMM via 3 bf16 products: Ah*Wh + Al*Wh + Ah*Wl.
__device__ __forceinline__ void gemm_full(const float* __restrict__ Wg,
                                          const char* A_hi, const char* A_lo,
                                          char* W_t, float acc[2][8][4],
                                          int r0, int c0, int qid, int tg, int tid) {
    #pragma unroll
    for (int mt = 0; mt < 2; mt++)
        #pragma unroll
        for (int nt = 0; nt < 8; nt++)
            #pragma unroll
            for (int i = 0; i < 4; i++) acc[mt][nt][i] = 0.f;

    __syncthreads();                  // prior users of W_t done
    convert_w(Wg, W_t, false, tid);
    __syncthreads();
    gemm_product(A_hi, W_t, acc, r0, c0, qid, tg);
    gemm_product(A_lo, W_t, acc, r0, c0, qid, tg);
    __syncthreads();
    convert_w(Wg, W_t, true, tid);
    __syncthreads();
    gemm_product(A_hi, W_t, acc, r0, c0, qid, tg);
}

// Rope + elu + 1 on accumulators (adds bias first). Pairs (j, j+8) sit in
// adjacent n-tiles of the same thread.
__device__ __forceinline__ void rope_elu_acc(float acc[2][8][4],
                                             const float* bias_s, int c0, int tg,
                                             const float sn[4][2], const float cs[4][2]) {
    #pragma unroll
    for (int mt = 0; mt < 2; mt++)
        #pragma unroll
        for (int t = 0; t < 4; t++)
            #pragma unroll
            for (int i = 0; i < 4; i++) {
                int ridx = mt * 2 + (i >> 1);
                int jj = i & 1;
                float x1 = acc[mt][2 * t][i]     + bias_s[c0 + t * 16 + tg * 2 + jj];
                float x2 = acc[mt][2 * t + 1][i] + bias_s[c0 + t * 16 + 8 + tg * 2 + jj];
                float s = sn[ridx][jj], c = cs[ridx][jj];
                float y1 = x1 * c - x2 * s;
                float y2 = x1 * s + x2 * c;
                acc[mt][2 * t][i]     = y1 > 0.f ? y1 + 1.f : expf(y1);
                acc[mt][2 * t + 1][i] = y2 > 0.f ? y2 + 1.f : expf(y2);
            }
}

// Store accumulators to an fp32 smem tile [128][128] with float4-block XOR
// swizzle: float index = row*128 + ((cb ^ (row&7))<<2) + (col&3), cb = col>>2.
__device__ __forceinline__ void acc_store(float* dst, const float acc[2][8][4],
                                          const float* bias_s, bool add_bias,
                                          int r0, int c0, int qid, int tg) {
    #pragma unroll
    for (int mt = 0; mt < 2; mt++)
        #pragma unroll
        for (int nt = 0; nt < 8; nt++)
            #pragma unroll
            for (int h2 = 0; h2 < 2; h2++) {
                int row = r0 + mt * 16 + h2 * 8 + qid;
                int col = c0 + nt * 8 + tg * 2;
                float v0 = acc[mt][nt][h2 * 2];
                float v1 = acc[mt][nt][h2 * 2 + 1];
                if (add_bias) { v0 += bias_s[col]; v1 += bias_s[col + 1]; }
                float* p = dst + row * 128 + (((col >> 2) ^ (row & 7)) << 2) + (col & 3);
                p[0] = v0; p[1] = v1;
            }
}

__device__ __forceinline__ void make_rope_tables(int t0, int r0, int qid, int tg,
                                                 float sn[4][2], float cs[4][2]) {
    const float invf[8] = {1.0f, 0.31622776601683794f, 0.1f, 0.03162277660168379f,
                           0.01f, 0.0031622776601683794f, 0.001f, 0.00031622776601683794f};
    #pragma unroll
    for (int ridx = 0; ridx < 4; ridx++) {
        int mt = ridx >> 1, half = ridx & 1;
        float tf = (float)(t0 + r0 + mt * 16 + half * 8 + qid);
        #pragma unroll
        for (int jj = 0; jj < 2; jj++)
            sincosf(tf * invf[tg * 2 + jj], &sn[ridx][jj], &cs[ridx][jj]);
    }
}

// ---------------------------------------------------------------------------
extern "C" __global__ void la_zero_scratch() {
    int i = blockIdx.x * blockDim.x + threadIdx.x;
    if (i < NB * NH * 256) g_ctx[i] = 0.f;
    if (i < NB * 128)      g_ksum[i] = 0.f;
}

// ---------------------------------------------------------------------------
// Pass 1: k = rope_elu(x@Wk+bk), v = x@Wv+bv; ctx += k^T v, ksum += k.
// smem: A_hi 32K | A_lo 32K | W_t 32K | k_s 64K | bias 512   (v_s aliases A)
// ---------------------------------------------------------------------------
#define P1_W    65536
#define P1_KS   98304
#define P1_BIAS 163840
#define P1_SMEM 164352

extern "C" __global__ void __launch_bounds__(256, 1)
la_kv(const float* __restrict__ x,
      const float* __restrict__ Wk, const float* __restrict__ bk,
      const float* __restrict__ Wv, const float* __restrict__ bv)
{
    extern __shared__ char sm[];
    char* A_hi = sm;
    char* A_lo = sm + 32768;
    char* W_t  = sm + P1_W;
    float* k_s    = (float*)(sm + P1_KS);
    float* v_s    = (float*)sm;          // alias of A region (used after GEMMs)
    float* bias_s = (float*)(sm + P1_BIAS);

    const int tid = threadIdx.x;
    const int wid = tid >> 5;
    const int lane = tid & 31;
    const int qid = lane >> 2, tg = lane & 3;
    const int r0 = (wid & 3) * 32;
    const int c0 = (wid >> 2) * 64;
    const int b  = blockIdx.y;
    const int t0 = blockIdx.x * TILE;

    // x tile -> bf16 hi/lo
    const float4* xp = (const float4*)(x + ((size_t)(b * NT + t0)) * ND);
    for (int i = tid; i < 4096; i += 256) {
        int row = i >> 5, k4 = i & 31;
        a_store4(A_hi, A_lo, row, k4, xp[i]);
    }
    float sn[4][2], cs[4][2];
    make_rope_tables(t0, r0, qid, tg, sn, cs);

    float acc[2][8][4];

    // ---- K GEMM ----
    if (tid < 128) bias_s[tid] = bk[tid];
    gemm_full(Wk, A_hi, A_lo, W_t, acc, r0, c0, qid, tg, tid);
    rope_elu_acc(acc, bias_s, c0, tg, sn, cs);
    acc_store(k_s, acc, bias_s, false, r0, c0, qid, tg);

    // ---- V GEMM ----
    __syncthreads();
    if (tid < 128) bias_s[tid] = bv[tid];
    gemm_full(Wv, A_hi, A_lo, W_t, acc, r0, c0, qid, tg, tid);
    __syncthreads();          // all A reads done before v_s overwrite
    acc_store(v_s, acc, bias_s, true, r0, c0, qid, tg);
    __syncthreads();

    // ---- ctx / ksum ----
    {
        int grp = tid >> 7, id = tid & 127;
        int h = id >> 4, d = id & 15;
        float accc[16];
        #pragma unroll
        for (int e = 0; e < 16; e++) accc[e] = 0.f;
        float ksacc = 0.f;
        int ts = grp * 64;
        int kcol = h * 16 + d;
        for (int t = ts; t < ts + 64; t++) {
            int sw = t & 7;
            float kv = k_s[t * 128 + ((((kcol >> 2) ^ sw) << 2) | (kcol & 3))];
            ksacc += kv;
            #pragma unroll
            for (int e4 = 0; e4 < 4; e4++) {
                float4 vv = *(const float4*)&v_s[t * 128 + (((h * 4 + e4) ^ sw) << 2)];
                accc[e4 * 4 + 0] = fmaf(kv, vv.x, accc[e4 * 4 + 0]);
                accc[e4 * 4 + 1] = fmaf(kv, vv.y, accc[e4 * 4 + 1]);
                accc[e4 * 4 + 2] = fmaf(kv, vv.z, accc[e4 * 4 + 2]);
                accc[e4 * 4 + 3] = fmaf(kv, vv.w, accc[e4 * 4 + 3]);
            }
        }
        float* cb = g_ctx + (size_t)b * NH * 256 + h * 256 + d * 16;
        #pragma unroll
        for (int e = 0; e < 16; e++) atomicAdd(cb + e, accc[e]);
        atomicAdd(g_ksum + b * 128 + kcol, ksacc);
    }
}

// ---------------------------------------------------------------------------
// Pass 2: q = rope_elu(x@Wq+bq); attn = (q@ctx)*z; out = attn@Wo + bo.
// smem: A_hi 32K | A_lo 32K | W_t 32K | q_s 64K | ctx 8K | ksum 512 | bias 512
// ---------------------------------------------------------------------------
#define P2_W    65536
#define P2_QS   98304
#define P2_CTX  163840
#define P2_KSUM 172032
#define P2_BIAS 172544
#define P2_SMEM 173056

extern "C" __global__ void __launch_bounds__(256, 1)
la_q(const float* __restrict__ x,
     const float* __restrict__ Wq, const float* __restrict__ bq,
     const float* __restrict__ Wo, const float* __restrict__ bo,
     float* __restrict__ out)
{
    extern __shared__ char sm[];
    char* A_hi = sm;
    char* A_lo = sm + 32768;
    char* W_t  = sm + P2_W;
    float* q_s    = (float*)(sm + P2_QS);    // also out staging
    float* ctx_s  = (float*)(sm + P2_CTX);
    float* ksum_s = (float*)(sm + P2_KSUM);
    float* bias_s = (float*)(sm + P2_BIAS);

    const int tid = threadIdx.x;
    const int wid = tid >> 5;
    const int lane = tid & 31;
    const int qid = lane >> 2, tg = lane & 3;
    const int r0 = (wid & 3) * 32;
    const int c0 = (wid >> 2) * 64;
    const int b  = blockIdx.y;
    const int t0 = blockIdx.x * TILE;

    const float4* xp = (const float4*)(x + ((size_t)(b * NT + t0)) * ND);
    for (int i = tid; i < 4096; i += 256) {
        int row = i >> 5, k4 = i & 31;
        a_store4(A_hi, A_lo, row, k4, xp[i]);
    }
    for (int i = tid; i < NH * 256; i += 256) ctx_s[i] = g_ctx[(size_t)b * NH * 256 + i];
    if (tid < 128) ksum_s[tid] = g_ksum[b * 128 + tid];

    float sn[4][2], cs[4][2];
    make_rope_tables(t0, r0, qid, tg, sn, cs);

    float acc[2][8][4];

    // ---- Q GEMM ----
    if (tid < 128) bias_s[tid] = bq[tid];
    gemm_full(Wq, A_hi, A_lo, W_t, acc, r0, c0, qid, tg, tid);
    rope_elu_acc(acc, bias_s, c0, tg, sn, cs);
    acc_store(q_s, acc, bias_s, false, r0, c0, qid, tg);
    __syncthreads();

    // ---- attention apply: writes attn into A tiles (bf16 hi/lo) ----
    {
        int r = tid >> 1, hg = tid & 1, swr = r & 7;
        #pragma unroll
        for (int hh = 0; hh < 4; hh++) {
            int h = hg * 4 + hh;
            float zz = 1e-6f;
            float oo[16];
            #pragma unroll
            for (int e = 0; e < 16; e++) oo[e] = 0.f;
            #pragma unroll
            for (int d = 0; d < 16; d++) {
                int col = h * 16 + d;
                float qv = q_s[r * 128 + ((((col >> 2) ^ swr) << 2) | (col & 3))];
                zz = fmaf(qv, ksum_s[col], zz);
                const float* cr = ctx_s + col * 16;
                #pragma unroll
                for (int e = 0; e < 16; e++) oo[e] = fmaf(qv, cr[e], oo[e]);
            }
            float zi = 1.f / zz;
            #pragma unroll
            for (int e4 = 0; e4 < 4; e4++) {
                int kcol = h * 16 + e4 * 4;
                a_store4(A_hi, A_lo, r, kcol >> 2,
                         make_float4(oo[e4 * 4] * zi, oo[e4 * 4 + 1] * zi,
                                     oo[e4 * 4 + 2] * zi, oo[e4 * 4 + 3] * zi));
            }
        }
    }

    // ---- O GEMM ----
    if (tid < 128) bias_s[tid] = bo[tid];
    gemm_full(Wo, A_hi, A_lo, W_t, acc, r0, c0, qid, tg, tid);
    __syncthreads();
    acc_store(q_s, acc, bias_s, true, r0, c0, qid, tg);
    __syncthreads();

    float4* outp = (float4*)(out + ((size_t)(b * NT + t0)) * ND);
    for (int i = tid; i < 4096; i += 256) {
        int row = i >> 5, cb = i & 31;
        outp[i] = *(const float4*)&q_s[row * 128 + ((cb ^ (row & 7)) << 2)];
    }
}

// ---------------------------------------------------------------------------
extern "C" void kernel_launch(void* const* d_in, const int* in_sizes, int n_in,
                              void* d_out, int out_size)
{
    const float* x  = (const float*)d_in[0];
    const float* Wq = (const float*)d_in[1];
    const float* bq = (const float*)d_in[2];
    const float* Wk = (const float*)d_in[3];
    const float* bk = (const float*)d_in[4];
    const float* Wv = (const float*)d_in[5];
    const float* bv = (const float*)d_in[6];
    const float* Wo = (const float*)d_in[7];
    const float* bo = (const float*)d_in[8];
    float* out = (float*)d_out;

    cudaFuncSetAttribute(la_kv, cudaFuncAttributeMaxDynamicSharedMemorySize, P1_SMEM);
    cudaFuncSetAttribute(la_q,  cudaFuncAttributeMaxDynamicSharedMemorySize, P2_SMEM);

    la_zero_scratch<<<(NB * NH * 256 + 255) / 256, 256>>>();

    dim3 grid(NT / TILE, NB);
    la_kv<<<grid, 256, P1_SMEM>>>(x, Wk, bk, Wv, bv);
    la_q<<<grid, 256, P2_SMEM>>>(x, Wq, bq, Wo, bo, out);
}

// round 4
// speedup vs baseline: 1.0796x; 1.0796x over previous
#include <cuda_runtime.h>
#include <cuda_bf16.h>
#include <math.h>
#include <stdint.h>

#define NB 8
#define NT 8192
#define ND 128
#define NH 8
#define TILE 128
#define NTILES 64              // NT / TILE

// ---------------- scratch (device globals; no allocs allowed) ---------------
static __device__ float g_q[NB * NT * ND];              // rope+elu'd q (33.5 MB)
static __device__ float g_part[NB * NTILES * 2 * 2048]; // per-(block,grp) ctx partials
static __device__ float g_partk[NB * NTILES * 2 * 128]; // per-(block,grp) ksum partials
static __device__ float g_ctx[NB * 2048];               // reduced [b][h][d][e]
static __device__ float g_ksum[NB * 128];               // reduced [b][h*16+d]

// ---------------------------------------------------------------------------
__device__ __forceinline__ void mma16816(float c[4], const uint32_t a[4],
                                         uint32_t b0, uint32_t b1) {
    asm volatile(
        "mma.sync.aligned.m16n8k16.row.col.f32.bf16.bf16.f32 "
        "{%0,%1,%2,%3}, {%4,%5,%6,%7}, {%8,%9}, {%0,%1,%2,%3};"
        : "+f"(c[0]), "+f"(c[1]), "+f"(c[2]), "+f"(c[3])
        : "r"(a[0]), "r"(a[1]), "r"(a[2]), "r"(a[3]), "r"(b0), "r"(b1));
}

// bf16 tile layout (A and W identical): [128 rows][128 bf16 = 256B], 16B-granule
// XOR swizzle: phys = row*256 + (((k>>3) ^ (row&7))<<4) + (k&7)*2.

__device__ __forceinline__ void a_store4(char* hi, char* lo, int row, int k4, float4 v) {
    uint32_t off = (uint32_t)(row * 256 + ((((k4 >> 1) ^ (row & 7)) << 4) | ((k4 & 1) << 3)));
    __nv_bfloat16 h0 = __float2bfloat16(v.x), h1 = __float2bfloat16(v.y);
    __nv_bfloat16 h2 = __float2bfloat16(v.z), h3 = __float2bfloat16(v.w);
    *(__nv_bfloat162*)(hi + off)     = __halves2bfloat162(h0, h1);
    *(__nv_bfloat162*)(hi + off + 4) = __halves2bfloat162(h2, h3);
    __nv_bfloat16 l0 = __float2bfloat16(v.x - __bfloat162float(h0));
    __nv_bfloat16 l1 = __float2bfloat16(v.y - __bfloat162float(h1));
    __nv_bfloat16 l2 = __float2bfloat16(v.z - __bfloat162float(h2));
    __nv_bfloat16 l3 = __float2bfloat16(v.w - __bfloat162float(h3));
    *(__nv_bfloat162*)(lo + off)     = __halves2bfloat162(l0, l1);
    *(__nv_bfloat162*)(lo + off + 4) = __halves2bfloat162(l2, l3);
}

// Convert W fp32 [k][n] row-major -> Wt_hi / Wt_lo [n][k] bf16 swizzled, one pass.
__device__ __forceinline__ void convert_w2(const float* __restrict__ W,
                                           char* wh, char* wl, int tid) {
    const float4* Wp = (const float4*)W;
    for (int i = tid; i < 4096; i += 256) {
        int k = i >> 5, n4 = i & 31;
        float4 w = Wp[i];
        float vv[4] = {w.x, w.y, w.z, w.w};
        #pragma unroll
        for (int u = 0; u < 4; u++) {
            int n = n4 * 4 + u;
            uint32_t off = (uint32_t)(n * 256 + ((((k >> 3) ^ (n & 7)) << 4) | ((k & 7) * 2)));
            __nv_bfloat16 bh = __float2bfloat16(vv[u]);
            __nv_bfloat16 bl = __float2bfloat16(vv[u] - __bfloat162float(bh));
            *(__nv_bfloat16*)(wh + off) = bh;
            *(__nv_bfloat16*)(wl + off) = bl;
        }
    }
}

// Fused 3-product GEMM: acc = Ah@Wh + Al@Wh + Ah@Wl (A frags loaded once per ks).
__device__ __forceinline__ void gemm3(const char* __restrict__ A_hi,
                                      const char* __restrict__ A_lo,
                                      const char* __restrict__ Wh,
                                      const char* __restrict__ Wl,
                                      float acc[2][8][4],
                                      int r0, int c0, int qid, int tg) {
    #pragma unroll
    for (int mt = 0; mt < 2; mt++)
        #pragma unroll
        for (int nt = 0; nt < 8; nt++)
            #pragma unroll
            for (int i = 0; i < 4; i++) acc[mt][nt][i] = 0.f;

    #pragma unroll
    for (int ks = 0; ks < 8; ks++) {
        const uint32_t g0 = (uint32_t)((((2 * ks) ^ qid) << 4) + tg * 4);
        const uint32_t g1 = (uint32_t)((((2 * ks + 1) ^ qid) << 4) + tg * 4);
        uint32_t Ah[2][4], Al[2][4];
        #pragma unroll
        for (int mt = 0; mt < 2; mt++) {
            const char* bh = A_hi + (r0 + mt * 16 + qid) * 256;
            const char* bl = A_lo + (r0 + mt * 16 + qid) * 256;
            Ah[mt][0] = *(const uint32_t*)(bh + g0);
            Ah[mt][1] = *(const uint32_t*)(bh + 8 * 256 + g0);
            Ah[mt][2] = *(const uint32_t*)(bh + g1);
            Ah[mt][3] = *(const uint32_t*)(bh + 8 * 256 + g1);
            Al[mt][0] = *(const uint32_t*)(bl + g0);
            Al[mt][1] = *(const uint32_t*)(bl + 8 * 256 + g0);
            Al[mt][2] = *(const uint32_t*)(bl + g1);
            Al[mt][3] = *(const uint32_t*)(bl + 8 * 256 + g1);
        }
        #pragma unroll
        for (int nt = 0; nt < 8; nt++) {
            const char* wb = (const char*)((c0 + nt * 8 + qid) * 256);
            uint32_t bh0 = *(const uint32_t*)(Wh + (size_t)wb + g0);
            uint32_t bh1 = *(const uint32_t*)(Wh + (size_t)wb + g1);
            uint32_t bl0 = *(const uint32_t*)(Wl + (size_t)wb + g0);
            uint32_t bl1 = *(const uint32_t*)(Wl + (size_t)wb + g1);
            mma16816(acc[0][nt], Ah[0], bh0, bh1);
            mma16816(acc[1][nt], Ah[1], bh0, bh1);
            mma16816(acc[0][nt], Al[0], bh0, bh1);
            mma16816(acc[1][nt], Al[1], bh0, bh1);
            mma16816(acc[0][nt], Ah[0], bl0, bl1);
            mma16816(acc[1][nt], Ah[1], bl0, bl1);
        }
    }
}

// bias + RoPE + elu+1 on accumulators.
__device__ __forceinline__ void rope_elu_acc(float acc[2][8][4],
                                             const float* bias_s, int c0, int tg,
                                             const float sn[4][2], const float cs[4][2]) {
    #pragma unroll
    for (int mt = 0; mt < 2; mt++)
        #pragma unroll
        for (int t = 0; t < 4; t++)
            #pragma unroll
            for (int i = 0; i < 4; i++) {
                int ridx = mt * 2 + (i >> 1);
                int jj = i & 1;
                float x1 = acc[mt][2 * t][i]     + bias_s[c0 + t * 16 + tg * 2 + jj];
                float x2 = acc[mt][2 * t + 1][i] + bias_s[c0 + t * 16 + 8 + tg * 2 + jj];
                float s = sn[ridx][jj], c = cs[ridx][jj];
                float y1 = x1 * c - x2 * s;
                float y2 = x1 * s + x2 * c;
                acc[mt][2 * t][i]     = y1 > 0.f ? y1 + 1.f : __expf(y1);
                acc[mt][2 * t + 1][i] = y2 > 0.f ? y2 + 1.f : __expf(y2);
            }
}

// Store accumulators to fp32 smem tile [128][128], float4-block XOR swizzle.
__device__ __forceinline__ void acc_store(float* dst, const float acc[2][8][4],
                                          const float* bias_s, bool add_bias,
                                          int r0, int c0, int qid, int tg) {
    #pragma unroll
    for (int mt = 0; mt < 2; mt++)
        #pragma unroll
        for (int nt = 0; nt < 8; nt++)
            #pragma unroll
            for (int h2 = 0; h2 < 2; h2++) {
                int row = r0 + mt * 16 + h2 * 8 + qid;
                int col = c0 + nt * 8 + tg * 2;
                float v0 = acc[mt][nt][h2 * 2];
                float v1 = acc[mt][nt][h2 * 2 + 1];
                if (add_bias) { v0 += bias_s[col]; v1 += bias_s[col + 1]; }
                float* p = dst + row * 128 + (((col >> 2) ^ (row & 7)) << 2) + (col & 3);
                p[0] = v0; p[1] = v1;
            }
}

__device__ __forceinline__ void make_rope_tables(int t0, int r0, int qid, int tg,
                                                 float sn[4][2], float cs[4][2]) {
    const float invf[8] = {1.0f, 0.31622776601683794f, 0.1f, 0.03162277660168379f,
                           0.01f, 0.0031622776601683794f, 0.001f, 0.00031622776601683794f};
    #pragma unroll
    for (int ridx = 0; ridx < 4; ridx++) {
        int mt = ridx >> 1, half = ridx & 1;
        float tf = (float)(t0 + r0 + mt * 16 + half * 8 + qid);
        #pragma unroll
        for (int jj = 0; jj < 2; jj++)
            sincosf(tf * invf[tg * 2 + jj], &sn[ridx][jj], &cs[ridx][jj]);
    }
}

// ---------------------------------------------------------------------------
// Kernel 1: K, Q, V GEMMs; k,v -> ctx/ksum partials; q -> g_q.
// smem: A_hi 32K | A_lo 32K | Wh 32K | Wl 32K | stage 64K | bias 1.5K
// ---------------------------------------------------------------------------
#define KVQ_WH    65536
#define KVQ_WL    98304
#define KVQ_STAGE 131072
#define KVQ_BIAS  196608
#define KVQ_SMEM  198144

extern "C" __global__ void __launch_bounds__(256, 1)
la_kvq(const float* __restrict__ x,
       const float* __restrict__ Wq, const float* __restrict__ bq,
       const float* __restrict__ Wk, const float* __restrict__ bk,
       const float* __restrict__ Wv, const float* __restrict__ bv)
{
    extern __shared__ char sm[];
    char* A_hi = sm;
    char* A_lo = sm + 32768;
    char* Wh   = sm + KVQ_WH;
    char* Wl   = sm + KVQ_WL;
    float* k_s = (float*)(sm + KVQ_STAGE);
    float* v_s = (float*)sm;                 // alias A (used after all GEMMs)
    float* bias_s = (float*)(sm + KVQ_BIAS); // [3][128]: k, q, v

    const int tid = threadIdx.x;
    const int wid = tid >> 5;
    const int lane = tid & 31;
    const int qid = lane >> 2, tg = lane & 3;
    const int r0 = (wid & 3) * 32;
    const int c0 = (wid >> 2) * 64;
    const int b  = blockIdx.y;
    const int t0 = blockIdx.x * TILE;

    // x tile -> bf16 hi/lo; biases
    const float4* xp = (const float4*)(x + ((size_t)(b * NT + t0)) * ND);
    for (int i = tid; i < 4096; i += 256) {
        int row = i >> 5, k4 = i & 31;
        a_store4(A_hi, A_lo, row, k4, xp[i]);
    }
    if (tid < 128) {
        bias_s[tid]       = bk[tid];
        bias_s[128 + tid] = bq[tid];
        bias_s[256 + tid] = bv[tid];
    }
    float sn[4][2], cs[4][2];
    make_rope_tables(t0, r0, qid, tg, sn, cs);

    float acc[2][8][4];

    // ---- K GEMM ----
    convert_w2(Wk, Wh, Wl, tid);
    __syncthreads();
    gemm3(A_hi, A_lo, Wh, Wl, acc, r0, c0, qid, tg);
    rope_elu_acc(acc, bias_s, c0, tg, sn, cs);
    acc_store(k_s, acc, bias_s, false, r0, c0, qid, tg);

    // ---- Q GEMM ----
    __syncthreads();
    convert_w2(Wq, Wh, Wl, tid);
    __syncthreads();
    gemm3(A_hi, A_lo, Wh, Wl, acc, r0, c0, qid, tg);
    rope_elu_acc(acc, bias_s + 128, c0, tg, sn, cs);
    {   // direct store to g_q (float2 per fragment pair)
        float* gq = g_q + ((size_t)(b * NT + t0)) * ND;
        #pragma unroll
        for (int mt = 0; mt < 2; mt++)
            #pragma unroll
            for (int nt = 0; nt < 8; nt++)
                #pragma unroll
                for (int h2 = 0; h2 < 2; h2++) {
                    int row = r0 + mt * 16 + h2 * 8 + qid;
                    int col = c0 + nt * 8 + tg * 2;
                    *(float2*)(gq + (size_t)row * ND + col) =
                        make_float2(acc[mt][nt][h2 * 2], acc[mt][nt][h2 * 2 + 1]);
                }
    }

    // ---- V GEMM ----
    __syncthreads();
    convert_w2(Wv, Wh, Wl, tid);
    __syncthreads();
    gemm3(A_hi, A_lo, Wh, Wl, acc, r0, c0, qid, tg);
    __syncthreads();                  // all A reads done before v_s overwrite
    acc_store(v_s, acc, bias_s + 256, true, r0, c0, qid, tg);
    __syncthreads();

    // ---- ctx / ksum partials (no atomics) ----
    {
        int grp = tid >> 7, id = tid & 127;
        int h = id >> 4, d = id & 15;
        float accc[16];
        #pragma unroll
        for (int e = 0; e < 16; e++) accc[e] = 0.f;
        float ksacc = 0.f;
        int ts = grp * 64;
        int kcol = h * 16 + d;
        for (int t = ts; t < ts + 64; t++) {
            int sw = t & 7;
            float kv = k_s[t * 128 + ((((kcol >> 2) ^ sw) << 2) | (kcol & 3))];
            ksacc += kv;
            #pragma unroll
            for (int e4 = 0; e4 < 4; e4++) {
                float4 vv = *(const float4*)&v_s[t * 128 + (((h * 4 + e4) ^ sw) << 2)];
                accc[e4 * 4 + 0] = fmaf(kv, vv.x, accc[e4 * 4 + 0]);
                accc[e4 * 4 + 1] = fmaf(kv, vv.y, accc[e4 * 4 + 1]);
                accc[e4 * 4 + 2] = fmaf(kv, vv.z, accc[e4 * 4 + 2]);
                accc[e4 * 4 + 3] = fmaf(kv, vv.w, accc[e4 * 4 + 3]);
            }
        }
        size_t slot = ((size_t)(b * NTILES + blockIdx.x) * 2 + grp);
        float* pp = g_part + slot * 2048 + h * 256 + d * 16;
        #pragma unroll
        for (int e = 0; e < 16; e++) pp[e] = accc[e];
        g_partk[slot * 128 + kcol] = ksacc;
    }
}

// ---------------------------------------------------------------------------
// Kernel 2: reduce partials. grid = NB blocks.
// ---------------------------------------------------------------------------
extern "C" __global__ void __launch_bounds__(256, 1)
la_red()
{
    int b = blockIdx.x;
    const float* pc = g_part + (size_t)b * NTILES * 2 * 2048;
    for (int e = threadIdx.x; e < 2048; e += 256) {
        float s = 0.f;
        for (int j = 0; j < NTILES * 2; j++) s += pc[(size_t)j * 2048 + e];
        g_ctx[b * 2048 + e] = s;
    }
    const float* pk = g_partk + (size_t)b * NTILES * 2 * 128;
    if (threadIdx.x < 128) {
        float s = 0.f;
        for (int j = 0; j < NTILES * 2; j++) s += pk[(size_t)j * 128 + threadIdx.x];
        g_ksum[b * 128 + threadIdx.x] = s;
    }
}

// ---------------------------------------------------------------------------
// Kernel 3: attn = (q@ctx)*z; out = attn@Wo + bo.
// smem: A 64K | Wh 32K | Wl 32K | stage 64K | ctx 8K | ksum 512 | bias 512
// ---------------------------------------------------------------------------
#define OUT_WH    65536
#define OUT_WL    98304
#define OUT_STAGE 131072
#define OUT_CTX   196608
#define OUT_KSUM  204800
#define OUT_BIAS  205312
#define OUT_SMEM  205824

extern "C" __global__ void __launch_bounds__(256, 1)
la_out(const float* __restrict__ Wo, const float* __restrict__ bo,
       float* __restrict__ out)
{
    extern __shared__ char sm[];
    char* A_hi = sm;
    char* A_lo = sm + 32768;
    char* Wh   = sm + OUT_WH;
    char* Wl   = sm + OUT_WL;
    float* q_s    = (float*)(sm + OUT_STAGE);   // q in, then out staging
    float* ctx_s  = (float*)(sm + OUT_CTX);
    float* ksum_s = (float*)(sm + OUT_KSUM);
    float* bias_s = (float*)(sm + OUT_BIAS);

    const int tid = threadIdx.x;
    const int wid = tid >> 5;
    const int lane = tid & 31;
    const int qid = lane >> 2, tg = lane & 3;
    const int r0 = (wid & 3) * 32;
    const int c0 = (wid >> 2) * 64;
    const int b  = blockIdx.y;
    const int t0 = blockIdx.x * TILE;

    const float4* qp = (const float4*)(g_q + ((size_t)(b * NT + t0)) * ND);
    for (int i = tid; i < 4096; i += 256) {
        int row = i >> 5, c4 = i & 31;
        float4 v = qp[i];
        *(float4*)&q_s[row * 128 + ((c4 ^ (row & 7)) << 2)] = v;
    }
    for (int i = tid; i < 2048; i += 256) ctx_s[i] = g_ctx[b * 2048 + i];
    if (tid < 128) { ksum_s[tid] = g_ksum[b * 128 + tid]; bias_s[tid] = bo[tid]; }
    convert_w2(Wo, Wh, Wl, tid);
    __syncthreads();

    // ---- attention apply: writes attn into A tiles (bf16 hi/lo) ----
    {
        int r = tid >> 1, hg = tid & 1, swr = r & 7;
        #pragma unroll
        for (int hh = 0; hh < 4; hh++) {
            int h = hg * 4 + hh;
            float zz = 1e-6f;
            float oo[16];
            #pragma unroll
            for (int e = 0; e < 16; e++) oo[e] = 0.f;
            #pragma unroll
            for (int d = 0; d < 16; d++) {
                int col = h * 16 + d;
                float qv = q_s[r * 128 + ((((col >> 2) ^ swr) << 2) | (col & 3))];
                zz = fmaf(qv, ksum_s[col], zz);
                const float* cr = ctx_s + col * 16;
                #pragma unroll
                for (int e = 0; e < 16; e++) oo[e] = fmaf(qv, cr[e], oo[e]);
            }
            float zi = 1.f / zz;
            #pragma unroll
            for (int e4 = 0; e4 < 4; e4++) {
                int kcol = h * 16 + e4 * 4;
                a_store4(A_hi, A_lo, r, kcol >> 2,
                         make_float4(oo[e4 * 4] * zi, oo[e4 * 4 + 1] * zi,
                                     oo[e4 * 4 + 2] * zi, oo[e4 * 4 + 3] * zi));
            }
        }
    }
    __syncthreads();

    // ---- O GEMM ----
    float acc[2][8][4];
    gemm3(A_hi, A_lo, Wh, Wl, acc, r0, c0, qid, tg);
    acc_store(q_s, acc, bias_s, true, r0, c0, qid, tg);
    __syncthreads();

    float4* outp = (float4*)(out + ((size_t)(b * NT + t0)) * ND);
    for (int i = tid; i < 4096; i += 256) {
        int row = i >> 5, cb = i & 31;
        outp[i] = *(const float4*)&q_s[row * 128 + ((cb ^ (row & 7)) << 2)];
    }
}

// ---------------------------------------------------------------------------
extern "C" void kernel_launch(void* const* d_in, const int* in_sizes, int n_in,
                              void* d_out, int out_size)
{
    const float* x  = (const float*)d_in[0];
    const float* Wq = (const float*)d_in[1];
    const float* bq = (const float*)d_in[2];
    const float* Wk = (const float*)d_in[3];
    const float* bk = (const float*)d_in[4];
    const float* Wv = (const float*)d_in[5];
    const float* bv = (const float*)d_in[6];
    const float* Wo = (const float*)d_in[7];
    const float* bo = (const float*)d_in[8];
    float* out = (float*)d_out;

    cudaFuncSetAttribute(la_kvq, cudaFuncAttributeMaxDynamicSharedMemorySize, KVQ_SMEM);
    cudaFuncSetAttribute(la_out, cudaFuncAttributeMaxDynamicSharedMemorySize, OUT_SMEM);

    dim3 grid(NT / TILE, NB);
    la_kvq<<<grid, 256, KVQ_SMEM>>>(x, Wq, bq, Wk, bk, Wv, bv);
    la_red<<<NB, 256>>>();
    la_out<<<grid, 256, OUT_SMEM>>>(Wo, bo, out);
}